// round 9
// baseline (speedup 1.0000x reference)
#include <cuda_runtime.h>
#include <math.h>

#define BB 4
#define LL 2048
#define DD 1024
#define MM (BB*LL)          // 8192 rows
#define PI_F 3.14159265358979323846f

// ---------------- scratch (device globals: allocation-free) ----------------
__device__ float g_xn  [(size_t)MM * DD];        // rmsnorm(x)
__device__ float g_u   [(size_t)MM * 3 * DD];    // in_proj output, (b*L+l, 3D)
__device__ float g_vg  [(size_t)BB * DD * LL];   // v*x1 after short conv, (b,d,l)
__device__ float g_x0  [(size_t)BB * DD * LL];   // x0 after short conv, (b,d,l)
__device__ float g_h2arr[(size_t)LL * 64];       // implicit filter hidden
__device__ float g_k   [(size_t)DD * LL];        // filter k, (d,l)
__device__ float g_yg  [(size_t)MM * DD];        // (y*x0) transposed to (b*L+l, d)
__device__ float g_hres[(size_t)MM * DD];        // h = out_proj(..)+x
__device__ float g_on  [(size_t)MM * DD];        // rmsnorm(h)
__device__ float g_ffn [(size_t)MM * 2 * DD];    // gelu(ffn1)

// ---------------- helpers ----------------
__device__ __forceinline__ float gelu_tanh(float x) {
    float x3 = x * x * x;
    return 0.5f * x * (1.f + tanhf(0.7978845608028654f * (x + 0.044715f * x3)));
}

// packed fp32x2 FMA (Blackwell FFMA2 — only reachable via PTX)
#define FMA2(d, a, b) asm("fma.rn.f32x2 %0, %1, %2, %0;" : "+l"(d) : "l"(a), "l"(b))

__device__ __forceinline__ unsigned long long ld_u64s(const float* p) {
    return *reinterpret_cast<const unsigned long long*>(p);
}

// ---------------- implicit filter: hidden layer h2 (L,64) ----------------
__global__ void k_h2(const float* __restrict__ w1, const float* __restrict__ b1,
                     const float* __restrict__ f1, const float* __restrict__ w2,
                     const float* __restrict__ b2, const float* __restrict__ f2) {
    const int l = blockIdx.x;
    const int j = threadIdx.x;          // 0..63
    __shared__ float sh1[64];
    const float t  = (float)l * (1.f / (float)(LL - 1));
    const float wv = 2.f * PI_F * (float)l * (1.f / (float)LL);
    const float ang = 1e-4f * wv;
    const float z1 = cosf(ang), z2 = -sinf(ang);
    float p = w1[j*3+0]*t + w1[j*3+1]*z1 + w1[j*3+2]*z2 + b1[j];
    sh1[j] = sinf(f1[j] * p);
    __syncthreads();
    float s = b2[j];
#pragma unroll
    for (int q = 0; q < 64; q++) s = fmaf(w2[j*64+q], sh1[q], s);
    g_h2arr[l*64 + j] = sinf(f2[j] * s);
}

// ---------------- implicit filter: k[d][l] = (h2 @ w3^T) * exp-mod ----------------
__global__ void __launch_bounds__(256) k_filterk(const float* __restrict__ w3) {
    const int l0 = blockIdx.x << 6;
    const int d0 = blockIdx.y << 6;
    __shared__ float h2s[64 * 65];
    __shared__ float w3s[64 * 64];
    for (int i = threadIdx.x; i < 4096; i += 256) {
        int r = i >> 6, c = i & 63;
        h2s[r*65 + c] = g_h2arr[(size_t)(l0 + r)*64 + c];
        w3s[i] = w3[((size_t)d0 << 6) + i];
    }
    __syncthreads();
    const int lt   = threadIdx.x & 63;
    const int dgrp = threadIdx.x >> 6;   // 0..3
    const int l = l0 + lt;
    const float t = (float)l * (1.f / (float)(LL - 1));
#pragma unroll 1
    for (int ii = 0; ii < 16; ii++) {
        const int dd = dgrp*16 + ii;
        float s = 0.f;
#pragma unroll
        for (int q = 0; q < 64; q++) s = fmaf(h2s[lt*65+q], w3s[dd*64+q], s);
        const int dglob = d0 + dd;
        const float absd = 3.070113457325394f + 12.280453829301576f * ((float)dglob * (1.f/1023.f));
        g_k[(size_t)dglob * LL + l] = s * expf(-t * absd);
    }
}

// ---------------- rmsnorm (one block per row) ----------------
__global__ void k_rmsnorm(const float* __restrict__ x, const float* __restrict__ w,
                          float* __restrict__ out) {
    const int row = blockIdx.x;
    const float* xr = x + (size_t)row * DD;
    float* orow = out + (size_t)row * DD;
    float s = 0.f;
    for (int i = threadIdx.x; i < DD; i += 256) { float v = xr[i]; s = fmaf(v, v, s); }
#pragma unroll
    for (int o = 16; o; o >>= 1) s += __shfl_xor_sync(0xffffffffu, s, o);
    __shared__ float red[8];
    if ((threadIdx.x & 31) == 0) red[threadIdx.x >> 5] = s;
    __syncthreads();
    float tt = 0.f;
#pragma unroll
    for (int i = 0; i < 8; i++) tt += red[i];
    const float scale = rsqrtf(tt * (1.f / (float)DD) + 1e-8f);
    for (int i = threadIdx.x; i < DD; i += 256) orow[i] = xr[i] * scale * w[i];
}

// ---------------- SGEMM (FFMA2): C[M,N] = A[M,K] @ W[N,K]^T + bias (+epilogue) ----
// EPI: 0 = bias only, 1 = bias + res, 2 = gelu(bias)
// As holds each a value DUPLICATED ({a,a} as a 64-bit pair) so the broadcast
// operand of fma.rn.f32x2 comes straight out of shared memory with zero MOVs.
#define AS_STRIDE 264
template<int EPI>
__global__ void __launch_bounds__(256, 2) sgemm_k(
    const float* __restrict__ A, const float* __restrict__ W,
    const float* __restrict__ bias, const float* __restrict__ res,
    float* __restrict__ C, int Mn, int Nn, int Kn)
{
    __shared__ float As[16][AS_STRIDE];   // duplicated: cols [2r,2r+1] = a_r
    __shared__ float Bs[16][128];
    const int tid = threadIdx.x;
    const int bm = blockIdx.y * 128;
    const int bn = blockIdx.x * 128;
    const int lr = tid >> 2;            // 0..63
    const int lc = (tid & 3) << 2;      // 0,4,8,12
    const int ty = tid >> 4;            // 0..15
    const int tx = tid & 15;            // 0..15
    const float* Ag = A + (size_t)(bm + lr) * Kn + lc;
    const float* Wg = W + (size_t)(bn + lr) * Kn + lc;

    unsigned long long acc[8][4];       // acc[i][jp] = {sum a_i*b_{2jp}, sum a_i*b_{2jp+1}}
#pragma unroll
    for (int i = 0; i < 8; i++)
#pragma unroll
        for (int j = 0; j < 4; j++) acc[i][j] = 0ull;

    // prologue: prefetch first K-tile into registers
    float4 a0 = *(const float4*)(Ag);
    float4 a1 = *(const float4*)(Ag + (size_t)64 * Kn);
    float4 w0 = *(const float4*)(Wg);
    float4 w1 = *(const float4*)(Wg + (size_t)64 * Kn);

    for (int k0 = 0; k0 < Kn; k0 += 16) {
        __syncthreads();
        // store A duplicated (STS.64), B transposed scalar
        *(float2*)&As[lc+0][2*lr]        = make_float2(a0.x, a0.x);
        *(float2*)&As[lc+1][2*lr]        = make_float2(a0.y, a0.y);
        *(float2*)&As[lc+2][2*lr]        = make_float2(a0.z, a0.z);
        *(float2*)&As[lc+3][2*lr]        = make_float2(a0.w, a0.w);
        *(float2*)&As[lc+0][2*(lr+64)]   = make_float2(a1.x, a1.x);
        *(float2*)&As[lc+1][2*(lr+64)]   = make_float2(a1.y, a1.y);
        *(float2*)&As[lc+2][2*(lr+64)]   = make_float2(a1.z, a1.z);
        *(float2*)&As[lc+3][2*(lr+64)]   = make_float2(a1.w, a1.w);
        Bs[lc+0][lr]    = w0.x; Bs[lc+1][lr]    = w0.y; Bs[lc+2][lr]    = w0.z; Bs[lc+3][lr]    = w0.w;
        Bs[lc+0][lr+64] = w1.x; Bs[lc+1][lr+64] = w1.y; Bs[lc+2][lr+64] = w1.z; Bs[lc+3][lr+64] = w1.w;
        __syncthreads();

        // prefetch next K-tile (LDG latency hidden behind the 16-kk compute)
        if (k0 + 16 < Kn) {
            a0 = *(const float4*)(Ag + k0 + 16);
            a1 = *(const float4*)(Ag + (size_t)64 * Kn + k0 + 16);
            w0 = *(const float4*)(Wg + k0 + 16);
            w1 = *(const float4*)(Wg + (size_t)64 * Kn + k0 + 16);
        }

#pragma unroll
        for (int kk = 0; kk < 16; kk++) {
            unsigned long long av[8];
#pragma unroll
            for (int i = 0; i < 8; i++)
                av[i] = ld_u64s(&As[kk][ty*16 + 2*i]);      // {a_i, a_i}
            unsigned long long bv[4];
#pragma unroll
            for (int j = 0; j < 4; j++)
                bv[j] = ld_u64s(&Bs[kk][tx*8 + 2*j]);       // {b_2j, b_2j+1}
#pragma unroll
            for (int i = 0; i < 8; i++)
#pragma unroll
                for (int j = 0; j < 4; j++)
                    FMA2(acc[i][j], av[i], bv[j]);
        }
    }

#pragma unroll
    for (int i = 0; i < 8; i++) {
        const int m = bm + ty*8 + i;
        const size_t ro = (size_t)m * Nn;
#pragma unroll
        for (int j = 0; j < 4; j++) {
            const int n = bn + tx*8 + 2*j;
            float v0 = __uint_as_float((unsigned)(acc[i][j] & 0xffffffffull)) + bias[n];
            float v1 = __uint_as_float((unsigned)(acc[i][j] >> 32)) + bias[n+1];
            if (EPI == 1) { v0 += res[ro + n]; v1 += res[ro + n + 1]; }
            if (EPI == 2) { v0 = gelu_tanh(v0); v1 = gelu_tanh(v1); }
            C[ro + n]     = v0;
            C[ro + n + 1] = v1;
        }
    }
}

// ---------------- depthwise causal conv k=3 + gating prep ----------------
__global__ void k_shortconv(const float* __restrict__ sfw, const float* __restrict__ sfb) {
    const int b = blockIdx.z;
    const int d = (blockIdx.y << 5) + threadIdx.x;
    const int lbase = (blockIdx.x << 5) + threadIdx.y;
    const float* ub = g_u + (size_t)b * LL * (3*DD);
#pragma unroll
    for (int i = 0; i < 4; i++) {
        const int l = lbase + (i << 3);
        float r[3];
#pragma unroll
        for (int c = 0; c < 3; c++) {
            const int ch = c*DD + d;
            const float w0 = sfw[ch*3+0], w1 = sfw[ch*3+1], w2 = sfw[ch*3+2];
            const float um2 = (l >= 2) ? ub[(size_t)(l-2)*(3*DD) + ch] : 0.f;
            const float um1 = (l >= 1) ? ub[(size_t)(l-1)*(3*DD) + ch] : 0.f;
            const float u0  = ub[(size_t)l*(3*DD) + ch];
            r[c] = w0*um2 + w1*um1 + w2*u0 + sfb[ch];
        }
        const size_t o = ((size_t)b*DD + d)*LL + l;
        g_x0[o] = r[0];
        g_vg[o] = r[2] * r[1];
    }
}

// ---------------- long causal conv, one CTA per (b,d) ----------------
__global__ void __launch_bounds__(128) k_longconv(const float* __restrict__ fbias) {
    const int bd = blockIdx.x;
    const int b = bd >> 10;
    const int d = bd & (DD - 1);
    __shared__ __align__(16) float sv[LL];
    __shared__ float skp[LL + 8 + ((LL + 8) >> 5) + 1];
    const float* vp = g_vg + (size_t)bd * LL;
    const float* kp = g_k  + (size_t)d  * LL;
    const int tid = threadIdx.x;
    for (int i = tid; i < LL/4; i += 128)
        ((float4*)sv)[i] = ((const float4*)vp)[i];
    for (int idx = tid; idx < LL + 8; idx += 128) {
        float v = (idx < 8) ? 0.f : kp[idx - 8];
        skp[idx + (idx >> 5)] = v;
    }
    __syncthreads();
    const float bia = fbias[d];
    const float* x0p = g_x0 + (size_t)bd * LL;
    float* outp = g_yg + ((size_t)b * LL) * DD + d;

#pragma unroll
    for (int g = 0; g < 2; g++) {
        const int la = (g == 0) ? (tid << 3) : (2040 - (tid << 3));
        float acc[8];
#pragma unroll
        for (int j = 0; j < 8; j++) acc[j] = 0.f;
        const int mend = la + 8;
        for (int M0 = 0; M0 < mend; M0 += 8) {
            const int base = 1 + la - M0;
            float kr[15];
#pragma unroll
            for (int i = 0; i < 15; i++) {
                const int idx = base + i;
                kr[i] = skp[idx + (idx >> 5)];
            }
            float svr[8];
#pragma unroll
            for (int mm = 0; mm < 8; mm++) svr[mm] = sv[M0 + mm];
#pragma unroll
            for (int mm = 0; mm < 8; mm++)
#pragma unroll
                for (int j = 0; j < 8; j++)
                    acc[j] = fmaf(svr[mm], kr[7 - mm + j], acc[j]);
        }
#pragma unroll
        for (int j = 0; j < 8; j++) {
            const int l = la + j;
            const float y = fmaf(sv[l], bia, acc[j]);
            outp[(size_t)l * DD] = y * x0p[l];
        }
    }
}

// ---------------- launch ----------------
extern "C" void kernel_launch(void* const* d_in, const int* in_sizes, int n_in,
                              void* d_out, int out_size) {
    const float* x          = (const float*)d_in[0];
    const float* norm_in_w  = (const float*)d_in[1];
    const float* in_proj_w  = (const float*)d_in[2];
    const float* in_proj_b  = (const float*)d_in[3];
    const float* sfw        = (const float*)d_in[4];
    const float* sfb        = (const float*)d_in[5];
    const float* mlp_w1     = (const float*)d_in[6];
    const float* mlp_b1     = (const float*)d_in[7];
    const float* freq1      = (const float*)d_in[8];
    const float* mlp_w2     = (const float*)d_in[9];
    const float* mlp_b2     = (const float*)d_in[10];
    const float* freq2      = (const float*)d_in[11];
    const float* mlp_w3     = (const float*)d_in[12];
    const float* filter_bias= (const float*)d_in[13];
    const float* out_proj_w = (const float*)d_in[14];
    const float* out_proj_b = (const float*)d_in[15];
    const float* norm_w     = (const float*)d_in[16];
    const float* ffn_w1     = (const float*)d_in[17];
    const float* ffn_b1     = (const float*)d_in[18];
    const float* ffn_w2     = (const float*)d_in[19];
    const float* ffn_b2     = (const float*)d_in[20];
    float* out = (float*)d_out;

    float *p_xn, *p_u, *p_yg, *p_h, *p_o, *p_ffn;
    cudaGetSymbolAddress((void**)&p_xn,  g_xn);
    cudaGetSymbolAddress((void**)&p_u,   g_u);
    cudaGetSymbolAddress((void**)&p_yg,  g_yg);
    cudaGetSymbolAddress((void**)&p_h,   g_hres);
    cudaGetSymbolAddress((void**)&p_o,   g_on);
    cudaGetSymbolAddress((void**)&p_ffn, g_ffn);

    // implicit filter (independent of main path)
    k_h2<<<LL, 64>>>(mlp_w1, mlp_b1, freq1, mlp_w2, mlp_b2, freq2);
    k_filterk<<<dim3(LL/64, DD/64), 256>>>(mlp_w3);

    // main path
    k_rmsnorm<<<MM, 256>>>(x, norm_in_w, p_xn);
    sgemm_k<0><<<dim3(3*DD/128, MM/128), 256>>>(p_xn, in_proj_w, in_proj_b, nullptr,
                                                p_u, MM, 3*DD, DD);
    k_shortconv<<<dim3(LL/32, DD/32, BB), dim3(32, 8)>>>(sfw, sfb);
    k_longconv<<<BB*DD, 128>>>(filter_bias);
    sgemm_k<1><<<dim3(DD/128, MM/128), 256>>>(p_yg, out_proj_w, out_proj_b, x,
                                              p_h, MM, DD, DD);
    k_rmsnorm<<<MM, 256>>>(p_h, norm_w, p_o);
    sgemm_k<2><<<dim3(2*DD/128, MM/128), 256>>>(p_o, ffn_w1, ffn_b1, nullptr,
                                                p_ffn, MM, 2*DD, DD);
    sgemm_k<1><<<dim3(DD/128, MM/128), 256>>>(p_ffn, ffn_w2, ffn_b2, p_h,
                                              out, MM, DD, 2*DD);
}

// round 14
// speedup vs baseline: 2.1342x; 2.1342x over previous
#include <cuda_runtime.h>
#include <cuda_bf16.h>
#include <math.h>
#include <stdint.h>

#define BB 4
#define LL 2048
#define DD 1024
#define MM (BB*LL)          // 8192 rows
#define PI_F 3.14159265358979323846f

// ---------------- scratch (device globals: allocation-free) ----------------
__device__ float g_xn  [(size_t)MM * DD];        // rmsnorm(x)
__device__ float g_u   [(size_t)MM * 3 * DD];    // in_proj output, (b*L+l, 3D)
__device__ float g_vg  [(size_t)BB * DD * LL];   // v*x1 after short conv, (b,d,l)
__device__ float g_x0  [(size_t)BB * DD * LL];   // x0 after short conv, (b,d,l)
__device__ float g_h2arr[(size_t)LL * 64];       // implicit filter hidden
__device__ float g_k   [(size_t)DD * LL];        // filter k, (d,l)
__device__ float g_yg  [(size_t)MM * DD];        // (y*x0) transposed to (b*L+l, d)
__device__ float g_hres[(size_t)MM * DD];        // h = out_proj(..)+x
__device__ float g_on  [(size_t)MM * DD];        // rmsnorm(h)
__device__ float g_ffn [(size_t)MM * 2 * DD];    // gelu(ffn1)

// bf16 split buffers: activations [hi | lo | hi]; weights [hi | hi | lo]
__device__ __nv_bfloat16 g_abf [(size_t)MM * 6 * DD];          // max: FFN2 A' (8192 x 6144)
__device__ __nv_bfloat16 g_wip [(size_t)(3*DD) * (3*DD)];      // in_proj W'
__device__ __nv_bfloat16 g_wop [(size_t)DD * (3*DD)];          // out_proj W'
__device__ __nv_bfloat16 g_wf1 [(size_t)(2*DD) * (3*DD)];      // ffn1 W'
__device__ __nv_bfloat16 g_wf2 [(size_t)DD * (6*DD)];          // ffn2 W'

// ---------------- helpers ----------------
__device__ __forceinline__ float gelu_tanh(float x) {
    float x3 = x * x * x;
    return 0.5f * x * (1.f + tanhf(0.7978845608028654f * (x + 0.044715f * x3)));
}

__device__ __forceinline__ uint32_t smem_u32(const void* p) {
    uint32_t a;
    asm("{ .reg .u64 t; cvta.to.shared.u64 t, %1; cvt.u32.u64 %0, t; }" : "=r"(a) : "l"(p));
    return a;
}

// cp.async (sm_80+, base-target safe)
__device__ __forceinline__ void cp16(uint32_t dst, const void* src) {
    asm volatile("cp.async.cg.shared.global [%0], [%1], 16;" :: "r"(dst), "l"(src));
}
#define CP_COMMIT()  asm volatile("cp.async.commit_group;" ::: "memory")
#define CP_WAIT(n)   asm volatile("cp.async.wait_group %0;" :: "n"(n) : "memory")

// ldmatrix x4 (sm_75+)
__device__ __forceinline__ void ldsm4(uint32_t* r, uint32_t addr) {
    asm volatile("ldmatrix.sync.aligned.m8n8.x4.shared.b16 {%0,%1,%2,%3}, [%4];"
        : "=r"(r[0]), "=r"(r[1]), "=r"(r[2]), "=r"(r[3]) : "r"(addr));
}

// HMMA m16n8k16 bf16 -> fp32 (sm_80+)
__device__ __forceinline__ void mma16816(float* d, const uint32_t* a, const uint32_t* b) {
    asm volatile("mma.sync.aligned.m16n8k16.row.col.f32.bf16.bf16.f32 "
        "{%0,%1,%2,%3}, {%4,%5,%6,%7}, {%8,%9}, {%0,%1,%2,%3};"
        : "+f"(d[0]), "+f"(d[1]), "+f"(d[2]), "+f"(d[3])
        : "r"(a[0]), "r"(a[1]), "r"(a[2]), "r"(a[3]), "r"(b[0]), "r"(b[1]));
}

// ---------------- fp32 -> bf16 split, Y is [Mrows, 3*Kcols] ----------------
// ORDER 0 (activations): [hi | lo | hi]
// ORDER 1 (weights):     [hi | hi | lo]
// so A'.W'^T = Ahi.Whi + Alo.Whi + Ahi.Wlo
template<int ORDER>
__global__ void k_split(const float* __restrict__ X, __nv_bfloat16* __restrict__ Y,
                        int Mrows, int Kcols) {
    size_t idx = (size_t)blockIdx.x * blockDim.x + threadIdx.x;
    size_t total = (size_t)Mrows * Kcols >> 2;
    if (idx >= total) return;
    int kq = Kcols >> 2;
    int r  = (int)(idx / kq);
    int k4 = (int)(idx % kq) << 2;
    const float4 v = *(const float4*)(X + (size_t)r * Kcols + k4);
    float vv[4] = {v.x, v.y, v.z, v.w};
    __nv_bfloat16 h[4], l[4];
#pragma unroll
    for (int i = 0; i < 4; i++) {
        h[i] = __float2bfloat16(vv[i]);
        l[i] = __float2bfloat16(vv[i] - __bfloat162float(h[i]));
    }
    __nv_bfloat16* yr = Y + (size_t)r * (3 * Kcols);
    if (ORDER == 0) {
        *(float2*)(yr + k4)             = *(float2*)h;
        *(float2*)(yr + Kcols + k4)     = *(float2*)l;
        *(float2*)(yr + 2 * Kcols + k4) = *(float2*)h;
    } else {
        *(float2*)(yr + k4)             = *(float2*)h;
        *(float2*)(yr + Kcols + k4)     = *(float2*)h;
        *(float2*)(yr + 2 * Kcols + k4) = *(float2*)l;
    }
}

// ---------------- HMMA bf16 GEMM: C[M,N] = A'[M,K3] @ W'[N,K3]^T + bias (+epi) ----
// 128x128 CTA tile, 8 warps (2x4 -> 64x32 each), K-chunk 64 bf16, cp.async double buffer.
// Smem tiles: 128 rows x 128B, SW128 swizzle (16B chunk ci -> ci ^ (row&7)).
// EPI: 0 = bias, 1 = bias + res, 2 = gelu(bias)
#define KCHUNK 64
#define TILE_BYTES 16384
#define SMEM_GEMM (4*TILE_BYTES)     // A0,A1,B0,B1

template<int EPI>
__global__ void __launch_bounds__(256) gemm_bf16(
    const __nv_bfloat16* __restrict__ A, const __nv_bfloat16* __restrict__ W,
    const float* __restrict__ bias, const float* __restrict__ res,
    float* __restrict__ C, int Mn, int Nn, int K3)
{
    extern __shared__ char smem[];
    const uint32_t sb = smem_u32(smem);
    const int tid  = threadIdx.x;
    const int wid  = tid >> 5;
    const int lane = tid & 31;
    const int bm = blockIdx.y << 7;
    const int bn = blockIdx.x << 7;
    const int NC = K3 / KCHUNK;

    const int warp_m = wid & 1;        // 2 x 64
    const int warp_n = wid >> 1;       // 4 x 32

    // ---- cp.async assignment: thread -> (row, half); 64B each per tile ----
    const int row = tid >> 1;          // 0..127
    const int cs  = tid & 1;           // 0/1 -> k-halves of 64B
    const __nv_bfloat16* Ar = A + (size_t)(bm + row) * K3 + cs * 32;
    const __nv_bfloat16* Wr = W + (size_t)(bn + row) * K3 + cs * 32;
    uint32_t dsto[4];
#pragma unroll
    for (int i = 0; i < 4; i++) {
        int ci = cs * 4 + i;
        dsto[i] = row * 128 + ((ci ^ (row & 7)) << 4);
    }

    float acc[4][4][4];
#pragma unroll
    for (int mt = 0; mt < 4; mt++)
#pragma unroll
        for (int nt = 0; nt < 4; nt++)
#pragma unroll
            for (int q = 0; q < 4; q++) acc[mt][nt][q] = 0.f;

    // ---- ldmatrix address bases ----
    const int a_row = warp_m * 64 + (lane & 15);
    const int a_cs  = lane >> 4;
    const int b_row = warp_n * 32 + ((lane >> 4) << 3) + (lane & 7);
    const int b_cs  = (lane >> 3) & 1;

    // prologue: chunk 0 -> stage 0
#pragma unroll
    for (int i = 0; i < 4; i++) {
        cp16(sb + dsto[i],                Ar + i * 8);
        cp16(sb + 2*TILE_BYTES + dsto[i], Wr + i * 8);
    }
    CP_COMMIT();

    for (int c = 0; c < NC; c++) {
        const int s = c & 1;
        if (c + 1 < NC) {
            const __nv_bfloat16* pa = Ar + (size_t)(c + 1) * KCHUNK;
            const __nv_bfloat16* pw = Wr + (size_t)(c + 1) * KCHUNK;
            const uint32_t st = (c + 1) & 1;
#pragma unroll
            for (int i = 0; i < 4; i++) {
                cp16(sb + st*TILE_BYTES + dsto[i],                pa + i * 8);
                cp16(sb + 2*TILE_BYTES + st*TILE_BYTES + dsto[i], pw + i * 8);
            }
            CP_COMMIT();
            CP_WAIT(1);
        } else {
            CP_WAIT(0);
        }
        __syncthreads();

        const uint32_t aB = sb + s * TILE_BYTES;
        const uint32_t bB = sb + 2*TILE_BYTES + s * TILE_BYTES;
#pragma unroll
        for (int ks = 0; ks < 4; ks++) {
            uint32_t afr[4][4];
#pragma unroll
            for (int mt = 0; mt < 4; mt++) {
                const int r = a_row + mt * 16;
                const int ch = 2 * ks + a_cs;
                ldsm4(afr[mt], aB + r * 128 + ((ch ^ (r & 7)) << 4));
            }
            uint32_t bfr[4][2];
#pragma unroll
            for (int g = 0; g < 2; g++) {
                const int r = b_row + g * 16;
                const int ch = 2 * ks + b_cs;
                uint32_t t4[4];
                ldsm4(t4, bB + r * 128 + ((ch ^ (r & 7)) << 4));
                bfr[2*g][0]   = t4[0]; bfr[2*g][1]   = t4[1];
                bfr[2*g+1][0] = t4[2]; bfr[2*g+1][1] = t4[3];
            }
#pragma unroll
            for (int mt = 0; mt < 4; mt++)
#pragma unroll
                for (int nt = 0; nt < 4; nt++)
                    mma16816(acc[mt][nt], afr[mt], bfr[nt]);
        }
        __syncthreads();
    }

    // ---- epilogue ----
#pragma unroll
    for (int mt = 0; mt < 4; mt++) {
        const int m0 = bm + warp_m * 64 + mt * 16 + (lane >> 2);
#pragma unroll
        for (int nt = 0; nt < 4; nt++) {
            const int n = bn + warp_n * 32 + nt * 8 + 2 * (lane & 3);
            const float b0 = bias[n], b1 = bias[n + 1];
            float v0 = acc[mt][nt][0] + b0;
            float v1 = acc[mt][nt][1] + b1;
            float v2 = acc[mt][nt][2] + b0;
            float v3 = acc[mt][nt][3] + b1;
            const size_t r0 = (size_t)m0 * Nn + n;
            const size_t r1 = (size_t)(m0 + 8) * Nn + n;
            if (EPI == 1) {
                v0 += res[r0]; v1 += res[r0 + 1];
                v2 += res[r1]; v3 += res[r1 + 1];
            }
            if (EPI == 2) {
                v0 = gelu_tanh(v0); v1 = gelu_tanh(v1);
                v2 = gelu_tanh(v2); v3 = gelu_tanh(v3);
            }
            *(float2*)(C + r0) = make_float2(v0, v1);
            *(float2*)(C + r1) = make_float2(v2, v3);
        }
    }
}

// ---------------- implicit filter: hidden layer h2 (L,64) ----------------
__global__ void k_h2(const float* __restrict__ w1, const float* __restrict__ b1,
                     const float* __restrict__ f1, const float* __restrict__ w2,
                     const float* __restrict__ b2, const float* __restrict__ f2) {
    const int l = blockIdx.x;
    const int j = threadIdx.x;          // 0..63
    __shared__ float sh1[64];
    const float t  = (float)l * (1.f / (float)(LL - 1));
    const float wv = 2.f * PI_F * (float)l * (1.f / (float)LL);
    const float ang = 1e-4f * wv;
    const float z1 = cosf(ang), z2 = -sinf(ang);
    float p = w1[j*3+0]*t + w1[j*3+1]*z1 + w1[j*3+2]*z2 + b1[j];
    sh1[j] = sinf(f1[j] * p);
    __syncthreads();
    float s = b2[j];
#pragma unroll
    for (int q = 0; q < 64; q++) s = fmaf(w2[j*64+q], sh1[q], s);
    g_h2arr[l*64 + j] = sinf(f2[j] * s);
}

// ---------------- implicit filter: k[d][l] = (h2 @ w3^T) * exp-mod ----------------
__global__ void __launch_bounds__(256) k_filterk(const float* __restrict__ w3) {
    const int l0 = blockIdx.x << 6;
    const int d0 = blockIdx.y << 6;
    __shared__ float h2s[64 * 65];
    __shared__ float w3s[64 * 64];
    for (int i = threadIdx.x; i < 4096; i += 256) {
        int r = i >> 6, c = i & 63;
        h2s[r*65 + c] = g_h2arr[(size_t)(l0 + r)*64 + c];
        w3s[i] = w3[((size_t)d0 << 6) + i];
    }
    __syncthreads();
    const int lt   = threadIdx.x & 63;
    const int dgrp = threadIdx.x >> 6;   // 0..3
    const int l = l0 + lt;
    const float t = (float)l * (1.f / (float)(LL - 1));
#pragma unroll 1
    for (int ii = 0; ii < 16; ii++) {
        const int dd = dgrp*16 + ii;
        float s = 0.f;
#pragma unroll
        for (int q = 0; q < 64; q++) s = fmaf(h2s[lt*65+q], w3s[dd*64+q], s);
        const int dglob = d0 + dd;
        const float absd = 3.070113457325394f + 12.280453829301576f * ((float)dglob * (1.f/1023.f));
        g_k[(size_t)dglob * LL + l] = s * expf(-t * absd);
    }
}

// ---------------- rmsnorm (one block per row) ----------------
__global__ void k_rmsnorm(const float* __restrict__ x, const float* __restrict__ w,
                          float* __restrict__ out) {
    const int row = blockIdx.x;
    const float* xr = x + (size_t)row * DD;
    float* orow = out + (size_t)row * DD;
    float s = 0.f;
    for (int i = threadIdx.x; i < DD; i += 256) { float v = xr[i]; s = fmaf(v, v, s); }
#pragma unroll
    for (int o = 16; o; o >>= 1) s += __shfl_xor_sync(0xffffffffu, s, o);
    __shared__ float red[8];
    if ((threadIdx.x & 31) == 0) red[threadIdx.x >> 5] = s;
    __syncthreads();
    float tt = 0.f;
#pragma unroll
    for (int i = 0; i < 8; i++) tt += red[i];
    const float scale = rsqrtf(tt * (1.f / (float)DD) + 1e-8f);
    for (int i = threadIdx.x; i < DD; i += 256) orow[i] = xr[i] * scale * w[i];
}

// ---------------- depthwise causal conv k=3 + gating prep ----------------
__global__ void k_shortconv(const float* __restrict__ sfw, const float* __restrict__ sfb) {
    const int b = blockIdx.z;
    const int d = (blockIdx.y << 5) + threadIdx.x;
    const int lbase = (blockIdx.x << 5) + threadIdx.y;
    const float* ub = g_u + (size_t)b * LL * (3*DD);
#pragma unroll
    for (int i = 0; i < 4; i++) {
        const int l = lbase + (i << 3);
        float r[3];
#pragma unroll
        for (int c = 0; c < 3; c++) {
            const int ch = c*DD + d;
            const float w0 = sfw[ch*3+0], w1 = sfw[ch*3+1], w2 = sfw[ch*3+2];
            const float um2 = (l >= 2) ? ub[(size_t)(l-2)*(3*DD) + ch] : 0.f;
            const float um1 = (l >= 1) ? ub[(size_t)(l-1)*(3*DD) + ch] : 0.f;
            const float u0  = ub[(size_t)l*(3*DD) + ch];
            r[c] = w0*um2 + w1*um1 + w2*u0 + sfb[ch];
        }
        const size_t o = ((size_t)b*DD + d)*LL + l;
        g_x0[o] = r[0];
        g_vg[o] = r[2] * r[1];
    }
}

// ---------------- long causal conv, one CTA per (b,d) ----------------
__global__ void __launch_bounds__(128) k_longconv(const float* __restrict__ fbias) {
    const int bd = blockIdx.x;
    const int b = bd >> 10;
    const int d = bd & (DD - 1);
    __shared__ __align__(16) float sv[LL];
    __shared__ float skp[LL + 8 + ((LL + 8) >> 5) + 1];
    const float* vp = g_vg + (size_t)bd * LL;
    const float* kp = g_k  + (size_t)d  * LL;
    const int tid = threadIdx.x;
    for (int i = tid; i < LL/4; i += 128)
        ((float4*)sv)[i] = ((const float4*)vp)[i];
    for (int idx = tid; idx < LL + 8; idx += 128) {
        float v = (idx < 8) ? 0.f : kp[idx - 8];
        skp[idx + (idx >> 5)] = v;
    }
    __syncthreads();
    const float bia = fbias[d];
    const float* x0p = g_x0 + (size_t)bd * LL;
    float* outp = g_yg + ((size_t)b * LL) * DD + d;

#pragma unroll
    for (int g = 0; g < 2; g++) {
        const int la = (g == 0) ? (tid << 3) : (2040 - (tid << 3));
        float acc[8];
#pragma unroll
        for (int j = 0; j < 8; j++) acc[j] = 0.f;
        const int mend = la + 8;
        for (int M0 = 0; M0 < mend; M0 += 8) {
            const int base = 1 + la - M0;
            float kr[15];
#pragma unroll
            for (int i = 0; i < 15; i++) {
                const int idx = base + i;
                kr[i] = skp[idx + (idx >> 5)];
            }
            float svr[8];
#pragma unroll
            for (int mm = 0; mm < 8; mm++) svr[mm] = sv[M0 + mm];
#pragma unroll
            for (int mm = 0; mm < 8; mm++)
#pragma unroll
                for (int j = 0; j < 8; j++)
                    acc[j] = fmaf(svr[mm], kr[7 - mm + j], acc[j]);
        }
#pragma unroll
        for (int j = 0; j < 8; j++) {
            const int l = la + j;
            const float y = fmaf(sv[l], bia, acc[j]);
            outp[(size_t)l * DD] = y * x0p[l];
        }
    }
}

// ---------------- launch ----------------
static inline int split_blocks(int m, int k) {
    long long t = (long long)m * k / 4;
    return (int)((t + 255) / 256);
}

extern "C" void kernel_launch(void* const* d_in, const int* in_sizes, int n_in,
                              void* d_out, int out_size) {
    const float* x          = (const float*)d_in[0];
    const float* norm_in_w  = (const float*)d_in[1];
    const float* in_proj_w  = (const float*)d_in[2];
    const float* in_proj_b  = (const float*)d_in[3];
    const float* sfw        = (const float*)d_in[4];
    const float* sfb        = (const float*)d_in[5];
    const float* mlp_w1     = (const float*)d_in[6];
    const float* mlp_b1     = (const float*)d_in[7];
    const float* freq1      = (const float*)d_in[8];
    const float* mlp_w2     = (const float*)d_in[9];
    const float* mlp_b2     = (const float*)d_in[10];
    const float* freq2      = (const float*)d_in[11];
    const float* mlp_w3     = (const float*)d_in[12];
    const float* filter_bias= (const float*)d_in[13];
    const float* out_proj_w = (const float*)d_in[14];
    const float* out_proj_b = (const float*)d_in[15];
    const float* norm_w     = (const float*)d_in[16];
    const float* ffn_w1     = (const float*)d_in[17];
    const float* ffn_b1     = (const float*)d_in[18];
    const float* ffn_w2     = (const float*)d_in[19];
    const float* ffn_b2     = (const float*)d_in[20];
    float* out = (float*)d_out;

    float *p_xn, *p_u, *p_yg, *p_h, *p_o, *p_ffn;
    __nv_bfloat16 *p_abf, *p_wip, *p_wop, *p_wf1, *p_wf2;
    cudaGetSymbolAddress((void**)&p_xn,  g_xn);
    cudaGetSymbolAddress((void**)&p_u,   g_u);
    cudaGetSymbolAddress((void**)&p_yg,  g_yg);
    cudaGetSymbolAddress((void**)&p_h,   g_hres);
    cudaGetSymbolAddress((void**)&p_o,   g_on);
    cudaGetSymbolAddress((void**)&p_ffn, g_ffn);
    cudaGetSymbolAddress((void**)&p_abf, g_abf);
    cudaGetSymbolAddress((void**)&p_wip, g_wip);
    cudaGetSymbolAddress((void**)&p_wop, g_wop);
    cudaGetSymbolAddress((void**)&p_wf1, g_wf1);
    cudaGetSymbolAddress((void**)&p_wf2, g_wf2);

    cudaFuncSetAttribute(gemm_bf16<0>, cudaFuncAttributeMaxDynamicSharedMemorySize, SMEM_GEMM);
    cudaFuncSetAttribute(gemm_bf16<1>, cudaFuncAttributeMaxDynamicSharedMemorySize, SMEM_GEMM);
    cudaFuncSetAttribute(gemm_bf16<2>, cudaFuncAttributeMaxDynamicSharedMemorySize, SMEM_GEMM);

    // weight splits ([hi|hi|lo]) + implicit filter (independent of main path)
    k_split<1><<<split_blocks(3*DD, DD), 256>>>(in_proj_w,  p_wip, 3*DD, DD);
    k_split<1><<<split_blocks(DD, DD),   256>>>(out_proj_w, p_wop, DD,   DD);
    k_split<1><<<split_blocks(2*DD, DD), 256>>>(ffn_w1,     p_wf1, 2*DD, DD);
    k_split<1><<<split_blocks(DD, 2*DD), 256>>>(ffn_w2,     p_wf2, DD,   2*DD);
    k_h2<<<LL, 64>>>(mlp_w1, mlp_b1, freq1, mlp_w2, mlp_b2, freq2);
    k_filterk<<<dim3(LL/64, DD/64), 256>>>(mlp_w3);

    // main path (activations split [hi|lo|hi])
    k_rmsnorm<<<MM, 256>>>(x, norm_in_w, p_xn);
    k_split<0><<<split_blocks(MM, DD), 256>>>(p_xn, p_abf, MM, DD);
    gemm_bf16<0><<<dim3(3*DD/128, MM/128), 256, SMEM_GEMM>>>(
        p_abf, p_wip, in_proj_b, nullptr, p_u, MM, 3*DD, 3*DD);

    k_shortconv<<<dim3(LL/32, DD/32, BB), dim3(32, 8)>>>(sfw, sfb);
    k_longconv<<<BB*DD, 128>>>(filter_bias);

    k_split<0><<<split_blocks(MM, DD), 256>>>(p_yg, p_abf, MM, DD);
    gemm_bf16<1><<<dim3(DD/128, MM/128), 256, SMEM_GEMM>>>(
        p_abf, p_wop, out_proj_b, x, p_h, MM, DD, 3*DD);

    k_rmsnorm<<<MM, 256>>>(p_h, norm_w, p_o);
    k_split<0><<<split_blocks(MM, DD), 256>>>(p_o, p_abf, MM, DD);
    gemm_bf16<2><<<dim3(2*DD/128, MM/128), 256, SMEM_GEMM>>>(
        p_abf, p_wf1, ffn_b1, nullptr, p_ffn, MM, 2*DD, 3*DD);

    k_split<0><<<split_blocks(MM, 2*DD), 256>>>(p_ffn, p_abf, MM, 2*DD);
    gemm_bf16<1><<<dim3(DD/128, MM/128), 256, SMEM_GEMM>>>(
        p_abf, p_wf2, ffn_b2, p_h, out, MM, DD, 6*DD);
}